// round 17
// baseline (speedup 1.0000x reference)
#include <cuda_runtime.h>
#include <cuda_bf16.h>
#include <math.h>

// ---------------------------------------------------------------------------
// BUTDDecoder: B=128, K=36, V_DIM=2048, EMBED=1024, HID=1024, NTOKEN=10000,
// MAX_LEN=20 (T=19 decode steps).
//
// Round 17: the ENTIRE setup (converts, permute, x1p, W1 transpose, vmean,
// vproj/giv/gip0/Wfq/Wf2h GEMMs, fused biases, zero-init) moved into the
// persistent kernel as prologue phases P0/P0b/P1/P2. Host = meta + loop.
// ---------------------------------------------------------------------------

#define B_     128
#define KOBJ   36
#define VD     2048
#define EMB    1024
#define HID_   1024
#define NTOK   10000
#define MAXLEN 20
#define TT     19
#define H3     3072
#define NCTA   296
#define W2TILES 157          // ceil(10000/64)
#define D1     (HID_ + VD + EMB)   // 4096, Wih1 row stride

typedef unsigned long long ull;
typedef __nv_bfloat16 bf16;

// ------------------------- scratch (device globals) ------------------------
__device__ float g_vs[B_ * KOBJ * VD];
__device__ float g_vproj[B_ * KOBJ * HID_];
__device__ float g_giv[B_ * H3];
__device__ float g_gipA[B_ * H3], g_gipB[B_ * H3];
__device__ float g_h1[B_ * HID_];
__device__ float g_h2all[(TT + 1) * B_ * HID_];
__device__ float g_gih[2][B_ * H3];
__device__ float g_gh1[2][B_ * H3];
__device__ float g_gh2[2][B_ * H3];
__device__ float g_qp[2][B_ * HID_];
__device__ float g_gi2h[2][B_ * H3];
__device__ float g_p0[4][B_ * H3];
__device__ float g_Wfq[HID_ * HID_];
__device__ float g_Wf2h[H3 * HID_];
__device__ float g_bfq[HID_];
__device__ float g_bi2f[H3];
__device__ int   g_order[B_];
__device__ int   g_dl[B_];
__device__ float g_mask[TT * B_];
__device__ int          g_barc;
__device__ volatile int g_barg;

// bf16 hi/lo operand arrays (activations)
__device__ bf16 g_vs_h[B_ * KOBJ * VD],        g_vs_l[B_ * KOBJ * VD];
__device__ bf16 g_vm_h[B_ * VD],               g_vm_l[B_ * VD];
__device__ bf16 g_x1p_h[TT * B_ * EMB],        g_x1p_l[TT * B_ * EMB];
__device__ bf16 g_h1_h[B_ * HID_],             g_h1_l[B_ * HID_];
__device__ bf16 g_h2_h[(TT + 1) * B_ * HID_],  g_h2_l[(TT + 1) * B_ * HID_];
__device__ bf16 g_attv_h[B_ * VD],             g_attv_l[B_ * VD];

// bf16 hi/lo weight arrays
__device__ bf16 g_wih1h_h[H3 * HID_],  g_wih1h_l[H3 * HID_];   // Wih1[:, :1024]
__device__ bf16 g_w1v_h[H3 * VD],      g_w1v_l[H3 * VD];       // Wih1[:, 1024:3072]
__device__ bf16 g_w1p_h[H3 * EMB],     g_w1p_l[H3 * EMB];      // Wih1[:, 3072:4096]
__device__ bf16 g_whh1_h[H3 * HID_],   g_whh1_l[H3 * HID_];
__device__ bf16 g_whh2_h[H3 * HID_],   g_whh2_l[H3 * HID_];
__device__ bf16 g_wv_h[HID_ * VD],     g_wv_l[HID_ * VD];
__device__ bf16 g_wih2v_h[H3 * VD],    g_wih2v_l[H3 * VD];     // Wih2[:, :2048]
__device__ bf16 g_wih2x_h[H3 * HID_],  g_wih2x_l[H3 * HID_];   // Wih2[:, 2048:]
__device__ bf16 g_w2_h[NTOK * HID_],   g_w2_l[NTOK * HID_];
__device__ bf16 g_wq_h[HID_ * HID_],   g_wq_l[HID_ * HID_];
__device__ bf16 g_w1t_h[HID_ * HID_],  g_w1t_l[HID_ * HID_];
__device__ bf16 g_wfq_h[HID_ * HID_],  g_wfq_l[HID_ * HID_];
__device__ bf16 g_wf2h_h[H3 * HID_],   g_wf2h_l[H3 * HID_];

// --------------------------- small helpers ---------------------------------
__device__ __forceinline__ void split2(float x, bf16& h, bf16& l) {
    h = __float2bfloat16(x);
    l = __float2bfloat16(x - __bfloat162float(h));
}
__device__ __forceinline__ unsigned smem_u32(const void* p) {
    return (unsigned)__cvta_generic_to_shared(p);
}
__device__ __forceinline__ void cpa16(unsigned dst, const void* src, int sz) {
    asm volatile("cp.async.ca.shared.global [%0], [%1], 16, %2;"
                 :: "r"(dst), "l"(src), "r"(sz));
}

#define LDM_X4(r0, r1, r2, r3, addr) \
    asm volatile("ldmatrix.sync.aligned.m8n8.x4.shared.b16 {%0,%1,%2,%3}, [%4];" \
        : "=r"(r0), "=r"(r1), "=r"(r2), "=r"(r3) : "r"(addr))

#define MMA16816(c, a, b) \
    asm volatile("mma.sync.aligned.m16n8k16.row.col.f32.bf16.bf16.f32 " \
        "{%0,%1,%2,%3}, {%4,%5,%6,%7}, {%8,%9}, {%0,%1,%2,%3};" \
        : "+f"((c)[0]), "+f"((c)[1]), "+f"((c)[2]), "+f"((c)[3]) \
        : "r"((a)[0]), "r"((a)[1]), "r"((a)[2]), "r"((a)[3]), \
          "r"((b)[0]), "r"((b)[1]))

// ------------------ persistent-loop device machinery ------------------------
__device__ __forceinline__ void grid_bar()
{
    __syncthreads();
    if (threadIdx.x == 0) {
        int gen = g_barg;
        __threadfence();
        if (atomicAdd(&g_barc, 1) == NCTA - 1) {
            g_barc = 0;
            __threadfence();
            g_barg = gen + 1;
        } else {
            while (g_barg == gen) __nanosleep(32);
            __threadfence();
        }
    }
    __syncthreads();
}

#define LBUF 49152   // per-stage smem (Ah16K|Al16K|Bh8K|Bl8K), 2 stages

// one 128x64xK GEMM tile, 256 threads (8 warps: 4m x 2n), double-buffered.
// relu: apply max(0,.) after bias.
__device__ __noinline__ void gemm_task(
    const bf16* __restrict__ Ah0, const bf16* __restrict__ Al0, int lda,
    const bf16* __restrict__ Wh0, const bf16* __restrict__ Wl0, int ldw,
    float* __restrict__ C, int ldc, int bn0, int Ksz,
    const float* __restrict__ bias, int relu, char* dsm)
{
    const int tid = threadIdx.x, wid = tid >> 5, lane = tid & 31;
    const int wm = wid >> 1, wn = wid & 1;

    unsigned dbase = smem_u32(dsm);
    unsigned s0 = (dbase + 1023u) & ~1023u;
    unsigned sAh[2], sAl[2], sBh[2], sBl[2];
#pragma unroll
    for (int b = 0; b < 2; b++) {
        sAh[b] = s0 + b * LBUF;
        sAl[b] = sAh[b] + 16384;
        sBh[b] = sAl[b] + 16384;
        sBl[b] = sBh[b] + 8192;
    }

    const int lrow = tid >> 3;
    const int lch  = tid & 7;
    const bf16* Wb_h = Wh0 + (size_t)bn0 * ldw;
    const bf16* Wb_l = Wl0 + (size_t)bn0 * ldw;
    auto load_chunk = [&](int c, int buf) {
        const int c0 = c * 64;
#pragma unroll
        for (int i = 0; i < 4; i++) {
            int row = i * 32 + lrow;
            unsigned off = (unsigned)(row * 128) + (unsigned)(((lch ^ (row & 7)) * 16));
            cpa16(sAh[buf] + off, Ah0 + (size_t)row * lda + c0 + lch * 8, 16);
            cpa16(sAl[buf] + off, Al0 + (size_t)row * lda + c0 + lch * 8, 16);
        }
#pragma unroll
        for (int i = 0; i < 2; i++) {
            int row = i * 32 + lrow;
            unsigned off = (unsigned)(row * 128) + (unsigned)(((lch ^ (row & 7)) * 16));
            cpa16(sBh[buf] + off, Wb_h + (size_t)row * ldw + c0 + lch * 8, 16);
            cpa16(sBl[buf] + off, Wb_l + (size_t)row * ldw + c0 + lch * 8, 16);
        }
        asm volatile("cp.async.commit_group;");
    };

    float acc[2][4][4];
#pragma unroll
    for (int mi = 0; mi < 2; mi++)
#pragma unroll
        for (int nj = 0; nj < 4; nj++)
#pragma unroll
            for (int e = 0; e < 4; e++) acc[mi][nj][e] = 0.f;

    const int xorkey = lane & 7;
    const int nch = Ksz / 64;
    load_chunk(0, 0);

    for (int c = 0; c < nch; c++) {
        if (c + 1 < nch) {
            load_chunk(c + 1, (c + 1) & 1);
            asm volatile("cp.async.wait_group 1;");
        } else {
            asm volatile("cp.async.wait_group 0;");
        }
        __syncthreads();
        const unsigned tAh = sAh[c & 1], tAl = sAl[c & 1];
        const unsigned tBh = sBh[c & 1], tBl = sBl[c & 1];

#pragma unroll
        for (int ks = 0; ks < 4; ks++) {
            unsigned Ahf[2][4], Alf[2][4];
            {
                const int arow = wm * 32 + (lane & 15);
                const unsigned aoff =
                    (unsigned)((((2 * ks) + (lane >> 4)) ^ xorkey) * 16);
#pragma unroll
                for (int mi = 0; mi < 2; mi++) {
                    unsigned ad = (unsigned)((arow + mi * 16) * 128) + aoff;
                    LDM_X4(Ahf[mi][0], Ahf[mi][1], Ahf[mi][2], Ahf[mi][3], tAh + ad);
                    LDM_X4(Alf[mi][0], Alf[mi][1], Alf[mi][2], Alf[mi][3], tAl + ad);
                }
            }
            unsigned Bh[4][2], Bl[4][2];
            {
                const int brow = wn * 32 + (lane & 7) + ((lane >> 4) << 3);
                const unsigned boff =
                    (unsigned)((((2 * ks) + ((lane >> 3) & 1)) ^ xorkey) * 16);
                unsigned r0, r1, r2, r3;
                unsigned b0 = (unsigned)(brow * 128) + boff;
                LDM_X4(r0, r1, r2, r3, tBh + b0);
                Bh[0][0] = r0; Bh[0][1] = r1; Bh[1][0] = r2; Bh[1][1] = r3;
                LDM_X4(r0, r1, r2, r3, tBh + b0 + 16 * 128);
                Bh[2][0] = r0; Bh[2][1] = r1; Bh[3][0] = r2; Bh[3][1] = r3;
                LDM_X4(r0, r1, r2, r3, tBl + b0);
                Bl[0][0] = r0; Bl[0][1] = r1; Bl[1][0] = r2; Bl[1][1] = r3;
                LDM_X4(r0, r1, r2, r3, tBl + b0 + 16 * 128);
                Bl[2][0] = r0; Bl[2][1] = r1; Bl[3][0] = r2; Bl[3][1] = r3;
            }
#pragma unroll
            for (int mi = 0; mi < 2; mi++)
#pragma unroll
                for (int nj = 0; nj < 4; nj++) {
                    MMA16816(acc[mi][nj], Ahf[mi], Bh[nj]);
                    MMA16816(acc[mi][nj], Ahf[mi], Bl[nj]);
                    MMA16816(acc[mi][nj], Alf[mi], Bh[nj]);
                }
        }
        __syncthreads();
    }

    const int g = lane >> 2, tig = lane & 3;
#pragma unroll
    for (int mi = 0; mi < 2; mi++)
#pragma unroll
        for (int nj = 0; nj < 4; nj++) {
            int row = wm * 32 + mi * 16 + g;
            int col = bn0 + wn * 32 + nj * 8 + 2 * tig;
            float v0 = acc[mi][nj][0], v1 = acc[mi][nj][1];
            float v2 = acc[mi][nj][2], v3 = acc[mi][nj][3];
            if (bias) {
                v0 += bias[col]; v1 += bias[col + 1];
                v2 += bias[col]; v3 += bias[col + 1];
            }
            if (relu) {
                v0 = fmaxf(v0, 0.f); v1 = fmaxf(v1, 0.f);
                v2 = fmaxf(v2, 0.f); v3 = fmaxf(v3, 0.f);
            }
            C[(size_t)row * ldc + col]           = v0;
            C[(size_t)row * ldc + col + 1]       = v1;
            C[(size_t)(row + 8) * ldc + col]     = v2;
            C[(size_t)(row + 8) * ldc + col + 1] = v3;
        }
}

// W2 tile for timestep ts, cols [bn0, bn0+64), K slice [kbase, kbase+64*nch).
// mode 0: raw partial; mode 1: += then bias+mask; mode 2: full single pass.
__device__ __noinline__ void gemm_task_w2(
    int ts, int bn0, int kbase, int nch, int mode,
    const float* __restrict__ b2, float* __restrict__ predict, char* dsm)
{
    const bf16* Ah0 = g_h2_h + (size_t)(ts + 1) * B_ * HID_ + kbase;
    const bf16* Al0 = g_h2_l + (size_t)(ts + 1) * B_ * HID_ + kbase;
    const int tid = threadIdx.x, wid = tid >> 5, lane = tid & 31;
    const int wm = wid >> 1, wn = wid & 1;

    unsigned dbase = smem_u32(dsm);
    unsigned s0 = (dbase + 1023u) & ~1023u;
    unsigned sAh[2], sAl[2], sBh[2], sBl[2];
#pragma unroll
    for (int b = 0; b < 2; b++) {
        sAh[b] = s0 + b * LBUF;
        sAl[b] = sAh[b] + 16384;
        sBh[b] = sAl[b] + 16384;
        sBl[b] = sBh[b] + 8192;
    }

    const int lrow = tid >> 3;
    const int lch  = tid & 7;
    auto load_chunk = [&](int c, int buf) {
        const int c0 = c * 64;
#pragma unroll
        for (int i = 0; i < 4; i++) {
            int row = i * 32 + lrow;
            unsigned off = (unsigned)(row * 128) + (unsigned)(((lch ^ (row & 7)) * 16));
            cpa16(sAh[buf] + off, Ah0 + (size_t)row * HID_ + c0 + lch * 8, 16);
            cpa16(sAl[buf] + off, Al0 + (size_t)row * HID_ + c0 + lch * 8, 16);
        }
#pragma unroll
        for (int i = 0; i < 2; i++) {
            int row = i * 32 + lrow;
            unsigned off = (unsigned)(row * 128) + (unsigned)(((lch ^ (row & 7)) * 16));
            int n = bn0 + row;
            int sz = (n < NTOK) ? 16 : 0;
            int nn = (n < NTOK) ? n : 0;
            cpa16(sBh[buf] + off, g_w2_h + (size_t)nn * HID_ + kbase + c0 + lch * 8, sz);
            cpa16(sBl[buf] + off, g_w2_l + (size_t)nn * HID_ + kbase + c0 + lch * 8, sz);
        }
        asm volatile("cp.async.commit_group;");
    };

    float acc[2][4][4];
#pragma unroll
    for (int mi = 0; mi < 2; mi++)
#pragma unroll
        for (int nj = 0; nj < 4; nj++)
#pragma unroll
            for (int e = 0; e < 4; e++) acc[mi][nj][e] = 0.f;

    const int xorkey = lane & 7;
    load_chunk(0, 0);

    for (int c = 0; c < nch; c++) {
        if (c + 1 < nch) {
            load_chunk(c + 1, (c + 1) & 1);
            asm volatile("cp.async.wait_group 1;");
        } else {
            asm volatile("cp.async.wait_group 0;");
        }
        __syncthreads();
        const unsigned tAh = sAh[c & 1], tAl = sAl[c & 1];
        const unsigned tBh = sBh[c & 1], tBl = sBl[c & 1];

#pragma unroll
        for (int ks = 0; ks < 4; ks++) {
            unsigned Ahf[2][4], Alf[2][4];
            {
                const int arow = wm * 32 + (lane & 15);
                const unsigned aoff =
                    (unsigned)((((2 * ks) + (lane >> 4)) ^ xorkey) * 16);
#pragma unroll
                for (int mi = 0; mi < 2; mi++) {
                    unsigned ad = (unsigned)((arow + mi * 16) * 128) + aoff;
                    LDM_X4(Ahf[mi][0], Ahf[mi][1], Ahf[mi][2], Ahf[mi][3], tAh + ad);
                    LDM_X4(Alf[mi][0], Alf[mi][1], Alf[mi][2], Alf[mi][3], tAl + ad);
                }
            }
            unsigned Bh[4][2], Bl[4][2];
            {
                const int brow = wn * 32 + (lane & 7) + ((lane >> 4) << 3);
                const unsigned boff =
                    (unsigned)((((2 * ks) + ((lane >> 3) & 1)) ^ xorkey) * 16);
                unsigned r0, r1, r2, r3;
                unsigned b0 = (unsigned)(brow * 128) + boff;
                LDM_X4(r0, r1, r2, r3, tBh + b0);
                Bh[0][0] = r0; Bh[0][1] = r1; Bh[1][0] = r2; Bh[1][1] = r3;
                LDM_X4(r0, r1, r2, r3, tBh + b0 + 16 * 128);
                Bh[2][0] = r0; Bh[2][1] = r1; Bh[3][0] = r2; Bh[3][1] = r3;
                LDM_X4(r0, r1, r2, r3, tBl + b0);
                Bl[0][0] = r0; Bl[0][1] = r1; Bl[1][0] = r2; Bl[1][1] = r3;
                LDM_X4(r0, r1, r2, r3, tBl + b0 + 16 * 128);
                Bl[2][0] = r0; Bl[2][1] = r1; Bl[3][0] = r2; Bl[3][1] = r3;
            }
#pragma unroll
            for (int mi = 0; mi < 2; mi++)
#pragma unroll
                for (int nj = 0; nj < 4; nj++) {
                    MMA16816(acc[mi][nj], Ahf[mi], Bh[nj]);
                    MMA16816(acc[mi][nj], Ahf[mi], Bl[nj]);
                    MMA16816(acc[mi][nj], Alf[mi], Bh[nj]);
                }
        }
        __syncthreads();
    }

    const int g = lane >> 2, tig = lane & 3;
#pragma unroll
    for (int mi = 0; mi < 2; mi++)
#pragma unroll
        for (int nj = 0; nj < 4; nj++) {
            int b0r = wm * 32 + mi * 16 + g;
            int col = bn0 + wn * 32 + nj * 8 + 2 * tig;
#pragma unroll
            for (int half = 0; half < 2; half++) {
                int b = b0r + half * 8;
                size_t orow = ((size_t)b * MAXLEN + ts) * NTOK;
                float v0 = acc[mi][nj][half * 2 + 0];
                float v1 = acc[mi][nj][half * 2 + 1];
                if (mode == 0) {
                    if (col < NTOK)     predict[orow + col]     = v0;
                    if (col + 1 < NTOK) predict[orow + col + 1] = v1;
                } else {
                    float m = g_mask[ts * B_ + b];
                    if (mode == 1) {
                        if (col < NTOK)
                            predict[orow + col] =
                                (predict[orow + col] + v0 + b2[col]) * m;
                        if (col + 1 < NTOK)
                            predict[orow + col + 1] =
                                (predict[orow + col + 1] + v1 + b2[col + 1]) * m;
                    } else {
                        if (col < NTOK)
                            predict[orow + col]     = (v0 + b2[col]) * m;
                        if (col + 1 < NTOK)
                            predict[orow + col + 1] = (v1 + b2[col + 1]) * m;
                    }
                }
            }
        }
}

// grid-strided fp32 -> bf16 hi/lo convert of a strided region
__device__ void conv_region(const float* __restrict__ src, int ld, int col0,
                            int rows, int cols, bf16* __restrict__ hi,
                            bf16* __restrict__ lo, int gid)
{
    size_t total = (size_t)rows * cols;
    for (size_t idx = gid; idx < total; idx += (size_t)NCTA * 256) {
        int r = (int)(idx / cols), c = (int)(idx % cols);
        split2(src[(size_t)r * ld + col0 + c], hi[idx], lo[idx]);
    }
}

// ---------------------------- kernel arguments ------------------------------
struct LA {
    const float *v, *caption;
    const float *Wih1, *Whh1, *bih1, *bhh1;
    const float *Wih2, *Whh2, *bih2, *bhh2;
    const float *Wv, *bv, *Wq, *bq, *wa, *ba, *W1, *b1, *W2, *b2;
    float *alphas, *predict;
};

// ------------------------- persistent loop kernel ---------------------------
__global__ void __launch_bounds__(256, 2) loop_kernel(LA a)
{
    extern __shared__ char dsm[];
    const int cta = blockIdx.x;
    const int tid = threadIdx.x;
    const int gid = cta * 256 + tid;
    const int GT  = NCTA * 256;

    // ======================= PROLOGUE (was host setup) ======================
    // ---- P0: zero-init, permute_v, x1p, W1 transpose, all weight converts --
    for (int idx = gid; idx < B_ * HID_; idx += GT) {
        g_h1[idx] = 0.f;    g_h1_h[idx] = __float2bfloat16(0.f); g_h1_l[idx] = __float2bfloat16(0.f);
        g_h2all[idx] = 0.f; g_h2_h[idx] = __float2bfloat16(0.f); g_h2_l[idx] = __float2bfloat16(0.f);
    }
    for (size_t idx = gid; idx < (size_t)B_ * KOBJ * VD; idx += GT) {
        int b = (int)(idx / ((size_t)KOBJ * VD));
        size_t rest = idx % ((size_t)KOBJ * VD);
        float x = a.v[(size_t)g_order[b] * KOBJ * VD + rest];
        g_vs[idx] = x;
        split2(x, g_vs_h[idx], g_vs_l[idx]);
    }
    for (size_t idx = gid; idx < (size_t)TT * B_ * EMB; idx += GT) {
        int c = (int)(idx % EMB);
        int r = (int)(idx / EMB);
        int t = r / B_, b = r % B_;
        float val = a.caption[((size_t)g_order[b] * MAXLEN + t) * EMB + c];
        split2(val, g_x1p_h[idx], g_x1p_l[idx]);
    }
    for (int idx = gid; idx < HID_ * HID_; idx += GT) {
        int j = idx / HID_, i = idx % HID_;
        split2(a.W1[(size_t)i * HID_ + j], g_w1t_h[idx], g_w1t_l[idx]);
    }
    conv_region(a.Wih1, D1,   1024, H3,   VD,   g_w1v_h,   g_w1v_l,   gid);
    conv_region(a.Wih1, D1,   3072, H3,   EMB,  g_w1p_h,   g_w1p_l,   gid);
    conv_region(a.Wih1, D1,   0,    H3,   HID_, g_wih1h_h, g_wih1h_l, gid);
    conv_region(a.Whh1, HID_, 0,    H3,   HID_, g_whh1_h,  g_whh1_l,  gid);
    conv_region(a.Whh2, HID_, 0,    H3,   HID_, g_whh2_h,  g_whh2_l,  gid);
    conv_region(a.Wv,   VD,   0,    HID_, VD,   g_wv_h,    g_wv_l,    gid);
    conv_region(a.Wih2, H3,   0,    H3,   VD,   g_wih2v_h, g_wih2v_l, gid);
    conv_region(a.Wih2, H3,   2048, H3,   HID_, g_wih2x_h, g_wih2x_l, gid);
    conv_region(a.Wq,   HID_, 0,    HID_, HID_, g_wq_h,    g_wq_l,    gid);
    conv_region(a.W2,   HID_, 0,    NTOK, HID_, g_w2_h,    g_w2_l,    gid);
    grid_bar();

    // ---- P0b: vmean -> vm hi/lo ----
    for (int idx = gid; idx < B_ * VD; idx += GT) {
        int b = idx / VD, d = idx % VD;
        const float* p = g_vs + (size_t)b * KOBJ * VD + d;
        float s = 0.f;
#pragma unroll 6
        for (int k = 0; k < KOBJ; k++) s += p[(size_t)k * VD];
        s *= (1.f / (float)KOBJ);
        split2(s, g_vm_h[idx], g_vm_l[idx]);
    }
    grid_bar();

    // ---- P1: setup GEMMs (1232 tasks striped over CTAs) ----
    //  [0,576)    vproj  : 36 mblk x 16 nt, K=2048, +bv, relu
    //  [576,624)  giv    : 48 nt,           K=2048, +bih1
    //  [624,720)  gip t=0: 2 slices x 48 nt, K=512
    //  [720,848)  Wfq    : 8 mblk x 16 nt,  K=1024
    //  [848,1232) Wf2h   : 24 mblk x 16 nt, K=1024
    for (int task = cta; task < 1232; task += NCTA) {
        if (task < 576) {
            int mblk = task / 16, nt = task % 16;
            gemm_task(g_vs_h + (size_t)mblk * 128 * VD,
                      g_vs_l + (size_t)mblk * 128 * VD, VD,
                      g_wv_h, g_wv_l, VD,
                      g_vproj + (size_t)mblk * 128 * HID_, HID_,
                      nt * 64, VD, a.bv, 1, dsm);
        } else if (task < 624) {
            int nt = task - 576;
            gemm_task(g_vm_h, g_vm_l, VD, g_w1v_h, g_w1v_l, VD,
                      g_giv, H3, nt * 64, VD, a.bih1, 0, dsm);
        } else if (task < 720) {
            int u = task - 624;
            int s = u / 48, nt = u % 48;
            int ko = s * 512;
            gemm_task(g_x1p_h + ko, g_x1p_l + ko, EMB,
                      g_w1p_h + ko, g_w1p_l + ko, EMB,
                      s ? g_gipB : g_gipA, H3, nt * 64, 512, nullptr, 0, dsm);
        } else if (task < 848) {
            int u = task - 720;
            int mblk = u / 16, nt = u % 16;
            gemm_task(g_wq_h + (size_t)mblk * 128 * HID_,
                      g_wq_l + (size_t)mblk * 128 * HID_, HID_,
                      g_w1t_h, g_w1t_l, HID_,
                      g_Wfq + (size_t)mblk * 128 * HID_, HID_,
                      nt * 64, HID_, nullptr, 0, dsm);
        } else {
            int u = task - 848;
            int mblk = u / 16, nt = u % 16;
            gemm_task(g_wih2x_h + (size_t)mblk * 128 * HID_,
                      g_wih2x_l + (size_t)mblk * 128 * HID_, HID_,
                      g_w1t_h, g_w1t_l, HID_,
                      g_Wf2h + (size_t)mblk * 128 * HID_, HID_,
                      nt * 64, HID_, nullptr, 0, dsm);
        }
    }
    grid_bar();

    // ---- P2: convert Wfq/Wf2h to bf16 hi/lo + fused biases ----
    conv_region(g_Wfq,  HID_, 0, HID_, HID_, g_wfq_h,  g_wfq_l,  gid);
    conv_region(g_Wf2h, HID_, 0, H3,   HID_, g_wf2h_h, g_wf2h_l, gid);
    for (int idx = gid; idx < HID_ + H3; idx += GT) {
        if (idx < HID_) {
            const float* w = a.Wq + (size_t)idx * HID_;
            float s = 0.f;
            for (int j = 0; j < HID_; j++) s += w[j] * a.b1[j];
            g_bfq[idx] = s + a.bq[idx];
        } else {
            int n = idx - HID_;
            const float* w = a.Wih2 + (size_t)n * H3 + VD;
            float s = 0.f;
            for (int j = 0; j < HID_; j++) s += w[j] * a.b1[j];
            g_bi2f[n] = s + a.bih2[n];
        }
    }
    grid_bar();

    // ============================ DECODE LOOP ===============================
    for (int t = 0; t < TT; t++) {
        const bf16*  h2ph = g_h2_h + (size_t)t * B_ * HID_;
        const bf16*  h2pl = g_h2_l + (size_t)t * B_ * HID_;
        const float* h2prev = g_h2all + (size_t)t * B_ * HID_;
        float*       h2next = g_h2all + (size_t)(t + 1) * B_ * HID_;

        // ---- phase 1: stage1 (gih, gh1, gh2), 288 tasks ----
        for (int task = cta; task < 288; task += NCTA) {
            int s = task & 1, x = (task >> 1) % 48, o = task / 96;
            int ko = s * 512;
            if (o == 0)
                gemm_task(h2ph + ko, h2pl + ko, HID_,
                          g_wih1h_h + ko, g_wih1h_l + ko, HID_,
                          g_gih[s], H3, x * 64, 512, nullptr, 0, dsm);
            else if (o == 1)
                gemm_task(g_h1_h + ko, g_h1_l + ko, HID_,
                          g_whh1_h + ko, g_whh1_l + ko, HID_,
                          g_gh1[s], H3, x * 64, 512,
                          s == 0 ? a.bhh1 : nullptr, 0, dsm);
            else
                gemm_task(h2ph + ko, h2pl + ko, HID_,
                          g_whh2_h + ko, g_whh2_l + ko, HID_,
                          g_gh2[s], H3, x * 64, 512,
                          s == 0 ? a.bhh2 : nullptr, 0, dsm);
        }
        grid_bar();

        // ---- phase 2: GRU1 pointwise (gi = giv + gipA + gipB + gih) ----
        for (int idx = gid; idx < B_ * HID_; idx += GT) {
            int b = idx >> 10, j = idx & 1023;
            size_t base = (size_t)b * H3 + j;
            float gr = g_giv[base] + g_gipA[base] + g_gipB[base]
                     + g_gih[0][base] + g_gih[1][base];
            float gz = g_giv[base + HID_] + g_gipA[base + HID_] + g_gipB[base + HID_]
                     + g_gih[0][base + HID_] + g_gih[1][base + HID_];
            float gn = g_giv[base + 2*HID_] + g_gipA[base + 2*HID_] + g_gipB[base + 2*HID_]
                     + g_gih[0][base + 2*HID_] + g_gih[1][base + 2*HID_];
            float ghr = g_gh1[0][base] + g_gh1[1][base];
            float ghz = g_gh1[0][base + HID_] + g_gh1[1][base + HID_];
            float ghn = g_gh1[0][base + 2*HID_] + g_gh1[1][base + 2*HID_];
            float r = 1.f / (1.f + expf(-(gr + ghr)));
            float z = 1.f / (1.f + expf(-(gz + ghz)));
            float n = tanhf(gn + r * ghn);
            float h = (1.f - z) * n + z * g_h1[idx];
            g_h1[idx] = h;
            split2(h, g_h1_h[idx], g_h1_l[idx]);
        }
        grid_bar();

        // ---- phase 3: stage2 (128 tasks) + W2 half-A (157, K 0..511) ----
        if (cta < 128) {
            int task = cta;
            if (task < 32) {
                int s = task & 1, x = (task >> 1);
                int ko = s * 512;
                gemm_task(g_h1_h + ko, g_h1_l + ko, HID_,
                          g_wfq_h + ko, g_wfq_l + ko, HID_,
                          g_qp[s], HID_, x * 64, 512, nullptr, 0, dsm);
            } else {
                int u = task - 32;
                int s = u & 1, x = (u >> 1);
                int ko = s * 512;
                gemm_task(g_h1_h + ko, g_h1_l + ko, HID_,
                          g_wf2h_h + ko, g_wf2h_l + ko, HID_,
                          g_gi2h[s], H3, x * 64, 512, nullptr, 0, dsm);
            }
        } else if (t > 0 && cta - 128 < W2TILES) {
            gemm_task_w2(t - 1, (cta - 128) * 64, 0, 8, 0, a.b2, a.predict, dsm);
        }
        grid_bar();

        // ---- phase 4: attention (128) + W2 half-B (157, K 512..1023) ----
        if (cta < B_) {
            int b = cta;
            float* qs  = (float*)dsm;
            float* att = qs + HID_;
            for (int d = tid; d < HID_; d += 256) {
                float qv = g_qp[0][b * HID_ + d] + g_qp[1][b * HID_ + d] + g_bfq[d];
                qs[d] = fmaxf(qv, 0.f) * a.wa[d];
            }
            __syncthreads();
            int warp = tid >> 5, lane = tid & 31;
            for (int k = warp; k < KOBJ; k += 8) {
                const float* vp = g_vproj + ((size_t)b * KOBJ + k) * HID_;
                float s = 0.f;
                for (int d = lane; d < HID_; d += 32) s += vp[d] * qs[d];
#pragma unroll
                for (int o = 16; o; o >>= 1) s += __shfl_down_sync(0xffffffffu, s, o);
                if (lane == 0) att[k] = s + a.ba[0];
            }
            __syncthreads();
            if (tid == 0) {
                float mx = att[0];
                for (int k = 1; k < KOBJ; k++) mx = fmaxf(mx, att[k]);
                float ssum = 0.f;
                for (int k = 0; k < KOBJ; k++) { float e = expf(att[k] - mx); att[k] = e; ssum += e; }
                float inv = 1.f / ssum;
                for (int k = 0; k < KOBJ; k++) att[k] *= inv;
            }
            __syncthreads();
            if (tid < KOBJ) {
                float m = (t < g_dl[b]) ? 1.f : 0.f;
                a.alphas[((size_t)b * MAXLEN + t) * KOBJ + tid] = att[tid] * m;
            }
            for (int d = tid; d < VD; d += 256) {
                const float* vb = g_vs + (size_t)b * KOBJ * VD + d;
                float s = 0.f;
#pragma unroll 6
                for (int k = 0; k < KOBJ; k++) s += att[k] * vb[(size_t)k * VD];
                split2(s, g_attv_h[b * VD + d], g_attv_l[b * VD + d]);
            }
        } else if (t > 0 && cta - 128 < W2TILES) {
            gemm_task_w2(t - 1, (cta - 128) * 64, 512, 8, 1, a.b2, a.predict, dsm);
        }
        grid_bar();

        // ---- phase 5: gi2att (192 tasks) + gip[t+1] (96 tasks) ----
        if (cta < 192) {
            int task = cta;
            int s = task & 3, x = task >> 2;
            int ko = s * 512;
            gemm_task(g_attv_h + ko, g_attv_l + ko, VD,
                      g_wih2v_h + ko, g_wih2v_l + ko, VD,
                      g_p0[s], H3, x * 64, 512, nullptr, 0, dsm);
        } else if (t + 1 < TT && cta - 192 < 96) {
            int u = cta - 192;
            int s = u & 1, x = u >> 1;
            int ko = s * 512;
            gemm_task(g_x1p_h + (size_t)(t + 1) * B_ * EMB + ko,
                      g_x1p_l + (size_t)(t + 1) * B_ * EMB + ko, EMB,
                      g_w1p_h + ko, g_w1p_l + ko, EMB,
                      s ? g_gipB : g_gipA, H3, x * 64, 512, nullptr, 0, dsm);
        }
        grid_bar();

        // ---- phase 6: GRU2 pointwise ----
        {
            bf16* hh = g_h2_h + (size_t)(t + 1) * B_ * HID_;
            bf16* hl = g_h2_l + (size_t)(t + 1) * B_ * HID_;
            for (int idx = gid; idx < B_ * HID_; idx += GT) {
                int b = idx >> 10, j = idx & 1023;
                size_t base = (size_t)b * H3 + j;
                float gr = g_bi2f[j], gz = g_bi2f[j + HID_], gn = g_bi2f[j + 2*HID_];
#pragma unroll
                for (int s = 0; s < 4; s++) {
                    gr += g_p0[s][base]; gz += g_p0[s][base + HID_]; gn += g_p0[s][base + 2*HID_];
                }
#pragma unroll
                for (int s = 0; s < 2; s++) {
                    gr += g_gi2h[s][base]; gz += g_gi2h[s][base + HID_]; gn += g_gi2h[s][base + 2*HID_];
                }
                float ghr = g_gh2[0][base] + g_gh2[1][base];
                float ghz = g_gh2[0][base + HID_] + g_gh2[1][base + HID_];
                float ghn = g_gh2[0][base + 2*HID_] + g_gh2[1][base + 2*HID_];
                float r = 1.f / (1.f + expf(-(gr + ghr)));
                float z = 1.f / (1.f + expf(-(gz + ghz)));
                float n = tanhf(gn + r * ghn);
                float h = (1.f - z) * n + z * h2prev[idx];
                h2next[idx] = h;
                split2(h, hh[idx], hl[idx]);
            }
        }
        grid_bar();
    }

    // ---- post-loop: final timestep's W2 + zero tails ----
    for (int task = cta; task < W2TILES; task += NCTA)
        gemm_task_w2(TT - 1, task * 64, 0, 16, 2, a.b2, a.predict, dsm);
    for (int idx = gid; idx < B_ * NTOK + B_ * KOBJ; idx += GT) {
        if (idx < B_ * NTOK) {
            int b = idx / NTOK, n = idx % NTOK;
            a.predict[((size_t)b * MAXLEN + (MAXLEN - 1)) * NTOK + n] = 0.f;
        } else {
            int r = idx - B_ * NTOK;
            int b = r / KOBJ, k = r % KOBJ;
            a.alphas[((size_t)b * MAXLEN + (MAXLEN - 1)) * KOBJ + k] = 0.f;
        }
    }
}

// ------------------------------- small kernels -----------------------------
__global__ void meta_kernel(const int* __restrict__ cap_len)
{
    int i = threadIdx.x;
    int ci = cap_len[i];
    int rank = 0;
    for (int j = 0; j < B_; j++) {
        int cj = cap_len[j];
        if (cj > ci || (cj == ci && j < i)) rank++;
    }
    g_order[rank] = i;
    __syncthreads();
    g_dl[i] = cap_len[g_order[i]] - 1;
    __syncthreads();
    int dli = g_dl[i];
    for (int t = 0; t < TT; t++) g_mask[t * B_ + i] = (t < dli) ? 1.f : 0.f;
    if (i == 0) { g_barc = 0; g_barg = 0; }
}

// --------------------------------- launch ----------------------------------
extern "C" void kernel_launch(void* const* d_in, const int* in_sizes, int n_in,
                              void* d_out, int out_size)
{
    LA a;
    a.v       = (const float*)d_in[0];
    a.caption = (const float*)d_in[1];
    const int* cap_len = (const int*)d_in[2];
    a.Wih1 = (const float*)d_in[3];
    a.Whh1 = (const float*)d_in[4];
    a.bih1 = (const float*)d_in[5];
    a.bhh1 = (const float*)d_in[6];
    a.Wih2 = (const float*)d_in[7];
    a.Whh2 = (const float*)d_in[8];
    a.bih2 = (const float*)d_in[9];
    a.bhh2 = (const float*)d_in[10];
    a.Wv   = (const float*)d_in[11];
    a.bv   = (const float*)d_in[12];
    a.Wq   = (const float*)d_in[13];
    a.bq   = (const float*)d_in[14];
    a.wa   = (const float*)d_in[15];
    a.ba   = (const float*)d_in[16];
    a.W1   = (const float*)d_in[17];
    a.b1   = (const float*)d_in[18];
    a.W2   = (const float*)d_in[19];
    a.b2   = (const float*)d_in[20];

    float* out  = (float*)d_out;
    a.predict   = out;
    a.alphas    = out + (size_t)B_ * MAXLEN * NTOK;

    const int LOOPSMEM = 2 * LBUF + 1024;   // 99328 B; 2 CTAs/SM
    cudaFuncSetAttribute(loop_kernel, cudaFuncAttributeMaxDynamicSharedMemorySize,
                         LOOPSMEM);

    meta_kernel<<<1, B_>>>(cap_len);
    loop_kernel<<<NCTA, 256, LOOPSMEM>>>(a);
}